// round 7
// baseline (speedup 1.0000x reference)
#include <cuda_runtime.h>
#include <cuda_bf16.h>

// CompositeLoss fused single-kernel: software-prefetch double buffer to
// break the load/compute convoy, log2-domain focal math.

#define PLANES   320          // B*C = 16*20
#define SEGS     4            // blocks per plane
#define THREADS  256          // 8 warps
#define F4_PLANE 16384        // HW/4
#define NTOT_D   20971520.0

// Per-plane moments: [mass, sty, stx, sp, spy, spx, spyy, spxx]
__device__ float        g_plane[PLANES * 8];
// Global sums: [fl(log2-scale), sum x^2, sum x*t, sum |x|]
__device__ double       g_glob[4];
__device__ unsigned int g_count;

__device__ __forceinline__ float frcp(float x) {
    float r; asm("rcp.approx.f32 %0, %1;" : "=f"(r) : "f"(x)); return r;
}
__device__ __forceinline__ float fex2(float x) {
    float r; asm("ex2.approx.f32 %0, %1;" : "=f"(r) : "f"(x)); return r;
}
__device__ __forceinline__ float flg2(float x) {
    float r; asm("lg2.approx.f32 %0, %1;" : "=f"(r) : "f"(x)); return r;
}

struct G4 { float psum, q1, q2, tsum, tq1; };

// Process one float4 pair (4 elements) in log2 domain.
__device__ __forceinline__ void proc4(const float4 pv, const float4 tv,
                                      float& fl, float& sqx, float& sxt, float& ab,
                                      G4& g)
{
    const float xv[4] = {pv.x, pv.y, pv.z, pv.w};
    const float tt[4] = {tv.x, tv.y, tv.z, tv.w};
    float p[4];
    #pragma unroll
    for (int j = 0; j < 4; j++) {
        const float x = xv[j];
        const float t = tt[j];                      // 0.0f or 1.0f
        const float m = x * -1.4426950408889634f;   // -x*log2(e)
        const float e = fex2(m);                    // e^{-x}
        const float s = e + 1.0f;
        const float r = frcp(s);                    // p = sigmoid(x)
        const float L = flg2(s);                    // lg2(1+e) = -lg2(p)
        // lg2(pt): t=1 -> -L ; t=0 -> m - L
        const float d  = m - L;
        const float lg = fmaf(t, -m, d);
        // u = 1 - pt: t=1 -> 1-p ; t=0 -> p
        const float k = fmaf(r, -2.0f, 1.0f);
        const float u = fmaf(t, k, r);
        const float a = fmaf(t, -0.5f, 0.75f);
        const float w = u * u;
        fl  = fmaf(a * w, lg, fl);                  // log2-scale; *ln2 at end
        sqx = fmaf(x, x, sqx);
        sxt = fmaf(x, t, sxt);
        ab += fabsf(x);
        p[j] = r;
    }
    g.psum = (p[0] + p[1]) + (p[2] + p[3]);
    g.q1   = fmaf(3.0f, p[3], fmaf(2.0f, p[2], p[1]));   // sum p_j * j
    g.q2   = fmaf(9.0f, p[3], fmaf(4.0f, p[2], p[1]));   // sum p_j * j^2
    g.tsum = (tt[0] + tt[1]) + (tt[2] + tt[3]);
    g.tq1  = fmaf(3.0f, tt[3], fmaf(2.0f, tt[2], tt[1]));
}

struct Acc {
    float fl, sqx, sxt, ab;
    float Pa, Pb, Q1a, Q2a, Q1b, Q2b;
    float spy, spyy;
    float Ta, Tb, TQ1a, TQ1b, sty;
};

__device__ __forceinline__ void row_body(const float4 pA, const float4 tA,
                                         const float4 pB, const float4 tB,
                                         const float y, Acc& c)
{
    G4 ga, gb;
    proc4(pA, tA, c.fl, c.sqx, c.sxt, c.ab, ga);
    proc4(pB, tB, c.fl, c.sqx, c.sxt, c.ab, gb);
    c.Pa += ga.psum;  c.Pb += gb.psum;
    c.Q1a += ga.q1;   c.Q2a += ga.q2;
    c.Q1b += gb.q1;   c.Q2b += gb.q2;
    c.Ta += ga.tsum;  c.Tb += gb.tsum;
    c.TQ1a += ga.tq1; c.TQ1b += gb.tq1;
    const float psum = ga.psum + gb.psum;
    const float tsum = ga.tsum + gb.tsum;
    const float mm   = psum * y;
    c.spy  += mm;
    c.spyy  = fmaf(mm, y, c.spyy);
    c.sty   = fmaf(tsum, y, c.sty);
}

__global__ __launch_bounds__(THREADS, 4) void composite_kernel(
    const float4* __restrict__ pred, const float4* __restrict__ tgt,
    float* __restrict__ out, int out_size)
{
    const int plane = blockIdx.x >> 2;
    const int seg   = blockIdx.x & 3;
    const int warp  = threadIdx.x >> 5;
    const int lane  = threadIdx.x & 31;

    const int   row0 = seg * 64 + warp * 8;     // 8 rows per warp
    const float x0a  = (float)(lane * 4);       // column group A base x
    const float x0b  = (float)(128 + lane * 4); // column group B base x

    // single running index; pred/tgt share layout
    const float4* __restrict__ pp = pred + (plane * F4_PLANE + row0 * 64 + lane);
    const float4* __restrict__ tp = tgt  + (plane * F4_PLANE + row0 * 64 + lane);

    Acc c = {};

    // prime the double buffer
    float4 cA = pp[0], cB = pp[32];
    float4 dA = tp[0], dB = tp[32];

    #pragma unroll 1
    for (int r = 0; r < 7; r++) {
        // prefetch next row BEFORE computing current (overlaps latency)
        const float4 nA = pp[64], nB = pp[96];
        const float4 mA = tp[64], mB = tp[96];
        row_body(cA, dA, cB, dB, (float)(row0 + r), c);
        cA = nA; cB = nB; dA = mA; dB = mB;
        pp += 64; tp += 64;
    }
    row_body(cA, dA, cB, dB, (float)(row0 + 7), c);

    // Per-thread x0 folds (x = x0 + j within each float4)
    const float sp   = c.Pa + c.Pb;
    const float spx  = fmaf(x0a, c.Pa, c.Q1a) + fmaf(x0b, c.Pb, c.Q1b);
    const float spxx = fmaf(x0a, fmaf(x0a, c.Pa, 2.0f * c.Q1a), c.Q2a)
                     + fmaf(x0b, fmaf(x0b, c.Pb, 2.0f * c.Q1b), c.Q2b);
    const float mass = c.Ta + c.Tb;
    const float stx  = fmaf(x0a, c.Ta, c.TQ1a) + fmaf(x0b, c.Tb, c.TQ1b);

    // ---- block reduction of 12 values ----
    float vals[12] = {c.fl, c.sqx, c.sxt, c.ab, mass, c.sty, stx,
                      sp, c.spy, spx, c.spyy, spxx};
    #pragma unroll
    for (int offm = 16; offm > 0; offm >>= 1) {
        #pragma unroll
        for (int k = 0; k < 12; k++)
            vals[k] += __shfl_down_sync(0xffffffffu, vals[k], offm);
    }
    __shared__ float smem[THREADS / 32][12];
    if (lane == 0) {
        #pragma unroll
        for (int k = 0; k < 12; k++) smem[warp][k] = vals[k];
    }
    __syncthreads();

    __shared__ bool s_last;
    if (threadIdx.x == 0) {
        float rr[12];
        #pragma unroll
        for (int k = 0; k < 12; k++) rr[k] = smem[0][k];
        for (int w = 1; w < THREADS / 32; w++)
            #pragma unroll
            for (int k = 0; k < 12; k++) rr[k] += smem[w][k];

        atomicAdd(&g_glob[0], (double)rr[0]);
        atomicAdd(&g_glob[1], (double)rr[1]);
        atomicAdd(&g_glob[2], (double)rr[2]);
        atomicAdd(&g_glob[3], (double)rr[3]);
        float* P = &g_plane[plane * 8];
        #pragma unroll
        for (int k = 0; k < 8; k++) atomicAdd(&P[k], rr[4 + k]);

        __threadfence();
        const unsigned cc = atomicAdd(&g_count, 1u);
        s_last = (cc == gridDim.x - 1);
    }
    __syncthreads();
    if (!s_last) return;

    // ---- last block: finalize + reset ----
    __threadfence();
    __shared__ float s_conc;
    __shared__ int   s_nv;
    if (threadIdx.x == 0) { s_conc = 0.f; s_nv = 0; }
    __syncthreads();

    for (int i = threadIdx.x; i < PLANES; i += THREADS) {
        const float* P = &g_plane[i * 8];
        const float m = P[0];
        if (m > 0.0f) {
            const float cy = P[1] / m;
            const float cx = P[2] / m;
            const float num = P[6] - 2.0f * cy * P[4] + cy * cy * P[3]
                            + P[7] - 2.0f * cx * P[5] + cx * cx * P[3];
            atomicAdd(&s_conc, num * (1.0f / 65536.0f));
            atomicAdd(&s_nv, 1);
        }
    }
    __syncthreads();

    if (threadIdx.x == 0) {
        double tmass = 0.0;
        for (int i = 0; i < PLANES; i++) tmass += (double)g_plane[i * 8];
        const double N = NTOT_D;
        const float focal    = (float)(-0.6931471805599453 * g_glob[0] / N);
        const double sq      = (g_glob[1] - 2.0 * g_glob[2] + tmass) / N;
        const float sparsity = (float)(sq + g_glob[3] / N);
        const float conc     = (s_nv > 0) ? (s_conc / (float)s_nv) : 0.0f;
        out[0] = focal + 0.8f * sparsity + 1.5f * conc;
        if (out_size >= 4) { out[1] = focal; out[2] = sparsity; out[3] = conc; }
    }
    __syncthreads();

    // reset accumulators for next launch (graph replay)
    for (int i = threadIdx.x; i < PLANES * 8; i += THREADS) g_plane[i] = 0.0f;
    if (threadIdx.x < 4) g_glob[threadIdx.x] = 0.0;
    if (threadIdx.x == 0) g_count = 0u;
}

extern "C" void kernel_launch(void* const* d_in, const int* in_sizes, int n_in,
                              void* d_out, int out_size) {
    const float4* pred = (const float4*)d_in[0];
    const float4* tgt  = (const float4*)d_in[1];
    composite_kernel<<<PLANES * SEGS, THREADS>>>(pred, tgt, (float*)d_out, out_size);
}

// round 8
// speedup vs baseline: 1.4676x; 1.4676x over previous
#include <cuda_runtime.h>
#include <cuda_bf16.h>

// CompositeLoss fused single-kernel, R7: flat fully-unrolled body (ptxas
// front-batches 32 LDG.128 for MLP), 80-reg budget (no spills),
// log2-domain focal math, merged A/B column-group moments.

#define PLANES   320          // B*C = 16*20
#define SEGS     4            // blocks per plane
#define THREADS  256          // 8 warps
#define F4_PLANE 16384        // HW/4
#define NTOT_D   20971520.0

// Per-plane moments: [mass, sty, stx, sp, spy, spx, spyy, spxx]
__device__ float        g_plane[PLANES * 8];
// Global sums: [fl(log2-scale), sum (x-t)^2, sum |x|]
__device__ double       g_glob[3];
__device__ unsigned int g_count;

__device__ __forceinline__ float frcp(float x) {
    float r; asm("rcp.approx.f32 %0, %1;" : "=f"(r) : "f"(x)); return r;
}
__device__ __forceinline__ float fex2(float x) {
    float r; asm("ex2.approx.f32 %0, %1;" : "=f"(r) : "f"(x)); return r;
}
__device__ __forceinline__ float flg2(float x) {
    float r; asm("lg2.approx.f32 %0, %1;" : "=f"(r) : "f"(x)); return r;
}

// Per-float4 core: focal/sparsity terms + group moments (p-sum, j-weighted
// p-moments, t-sum, j-weighted t-moment). j = within-float4 column offset.
__device__ __forceinline__ void grp4(const float4 pv, const float4 tv,
                                     float& fl, float& sq, float& ab,
                                     float& psum, float& q1, float& q2,
                                     float& tsum, float& tq1)
{
    const float xv[4] = {pv.x, pv.y, pv.z, pv.w};
    const float tt[4] = {tv.x, tv.y, tv.z, tv.w};
    float p[4];
    #pragma unroll
    for (int j = 0; j < 4; j++) {
        const float x = xv[j];
        const float t = tt[j];                      // 0.0f or 1.0f
        const float m = x * -1.4426950408889634f;   // -x*log2(e)
        const float e = fex2(m);                    // 2^m = e^{-x}
        const float s = e + 1.0f;
        const float r = frcp(s);                    // p = sigmoid(x)
        const float L = flg2(s);                    // -lg2(p)
        const float d2 = m - L;                     // lg2(1-p)
        const float lg = fmaf(t, -m, d2);           // lg2(pt)
        const float k = fmaf(r, -2.0f, 1.0f);
        const float u = fmaf(t, k, r);              // 1 - pt
        const float a = fmaf(t, -0.5f, 0.75f);      // alpha_t
        fl = fmaf(a * (u * u), lg, fl);             // (negative) log2-scale
        const float dd = x - t;
        sq = fmaf(dd, dd, sq);
        ab += fabsf(x);
        p[j] = r;
    }
    psum = (p[0] + p[1]) + (p[2] + p[3]);
    q1   = fmaf(3.0f, p[3], fmaf(2.0f, p[2], p[1]));
    q2   = fmaf(9.0f, p[3], fmaf(4.0f, p[2], p[1]));
    tsum = (tt[0] + tt[1]) + (tt[2] + tt[3]);
    tq1  = fmaf(3.0f, tt[3], fmaf(2.0f, tt[2], tt[1]));
}

__global__ __launch_bounds__(THREADS, 3) void composite_kernel(
    const float4* __restrict__ pred, const float4* __restrict__ tgt,
    float* __restrict__ out, int out_size)
{
    const int plane = blockIdx.x >> 2;
    const int seg   = blockIdx.x & 3;
    const int warp  = threadIdx.x >> 5;
    const int lane  = threadIdx.x & 31;

    const int   row0 = seg * 64 + warp * 8;   // 8 rows per warp
    const float x0   = (float)(lane * 4);     // group A base column; B = +128

    const int base = plane * F4_PLANE + row0 * 64 + lane;
    const float4* __restrict__ pp = pred + base;
    const float4* __restrict__ tp = tgt  + base;

    float fl = 0.f, sq = 0.f, ab = 0.f;
    float P = 0.f, Pb = 0.f, Q1 = 0.f, Q1b = 0.f, Q2 = 0.f;
    float spy = 0.f, spyy = 0.f;
    float T = 0.f, Tb = 0.f, TQ1 = 0.f, sty = 0.f;

    #pragma unroll
    for (int r = 0; r < 8; r++) {
        const float4 pA = pp[r * 64],      tA = tp[r * 64];
        const float4 pB = pp[r * 64 + 32], tB = tp[r * 64 + 32];

        float psA, q1A, q2A, tsA, tq1A;
        float psB, q1B, q2B, tsB, tq1B;
        grp4(pA, tA, fl, sq, ab, psA, q1A, q2A, tsA, tq1A);
        grp4(pB, tB, fl, sq, ab, psB, q1B, q2B, tsB, tq1B);

        const float rowp = psA + psB;
        const float rowt = tsA + tsB;
        P  += rowp;        Pb  += psB;
        Q1 += q1A + q1B;   Q1b += q1B;
        Q2 += q2A + q2B;
        T  += rowt;        Tb  += tsB;
        TQ1 += tq1A + tq1B;

        const float y = (float)(row0 + r);
        spy  = fmaf(rowp, y, spy);
        spyy = fmaf(rowp, y * y, spyy);   // y*y folds to a constant per r
        sty  = fmaf(rowt, y, sty);
    }

    // Per-thread x folds. For group B: x = xa + 128 with xa = x0 + j.
    const float sp   = P;
    const float spx  = fmaf(x0, P, fmaf(128.0f, Pb, Q1));
    const float sxa2 = fmaf(x0 * x0, P, fmaf(2.0f * x0, Q1, Q2)); // sum p*xa^2
    const float sbxa = fmaf(x0, Pb, Q1b);                         // sum_B p*xa
    const float spxx = fmaf(256.0f, sbxa, fmaf(16384.0f, Pb, sxa2));
    const float mass = T;
    const float stx  = fmaf(x0, T, fmaf(128.0f, Tb, TQ1));

    // ---- block reduction of 11 values ----
    float vals[11] = {fl, sq, ab, mass, sty, stx, sp, spy, spx, spyy, spxx};
    #pragma unroll
    for (int offm = 16; offm > 0; offm >>= 1) {
        #pragma unroll
        for (int k = 0; k < 11; k++)
            vals[k] += __shfl_down_sync(0xffffffffu, vals[k], offm);
    }
    __shared__ float smem[THREADS / 32][11];
    if (lane == 0) {
        #pragma unroll
        for (int k = 0; k < 11; k++) smem[warp][k] = vals[k];
    }
    __syncthreads();

    __shared__ bool s_last;
    if (threadIdx.x == 0) {
        float rr[11];
        #pragma unroll
        for (int k = 0; k < 11; k++) rr[k] = smem[0][k];
        for (int w = 1; w < THREADS / 32; w++)
            #pragma unroll
            for (int k = 0; k < 11; k++) rr[k] += smem[w][k];

        atomicAdd(&g_glob[0], (double)rr[0]);
        atomicAdd(&g_glob[1], (double)rr[1]);
        atomicAdd(&g_glob[2], (double)rr[2]);
        float* Pp = &g_plane[plane * 8];
        #pragma unroll
        for (int k = 0; k < 8; k++) atomicAdd(&Pp[k], rr[3 + k]);

        __threadfence();
        const unsigned cc = atomicAdd(&g_count, 1u);
        s_last = (cc == gridDim.x - 1);
    }
    __syncthreads();
    if (!s_last) return;

    // ---- last block: finalize + reset ----
    __threadfence();
    __shared__ float s_conc;
    __shared__ int   s_nv;
    if (threadIdx.x == 0) { s_conc = 0.f; s_nv = 0; }
    __syncthreads();

    for (int i = threadIdx.x; i < PLANES; i += THREADS) {
        const float* Pp = &g_plane[i * 8];
        const float m = Pp[0];
        if (m > 0.0f) {
            const float cy = Pp[1] / m;
            const float cx = Pp[2] / m;
            const float num = Pp[6] - 2.0f * cy * Pp[4] + cy * cy * Pp[3]
                            + Pp[7] - 2.0f * cx * Pp[5] + cx * cx * Pp[3];
            atomicAdd(&s_conc, num * (1.0f / 65536.0f));
            atomicAdd(&s_nv, 1);
        }
    }
    __syncthreads();

    if (threadIdx.x == 0) {
        const double N = NTOT_D;
        const float focal    = (float)(-0.6931471805599453 * g_glob[0] / N);
        const float sparsity = (float)((g_glob[1] + g_glob[2]) / N);
        const float conc     = (s_nv > 0) ? (s_conc / (float)s_nv) : 0.0f;
        out[0] = focal + 0.8f * sparsity + 1.5f * conc;
        if (out_size >= 4) { out[1] = focal; out[2] = sparsity; out[3] = conc; }
    }
    __syncthreads();

    // reset accumulators for next launch (graph replay)
    for (int i = threadIdx.x; i < PLANES * 8; i += THREADS) g_plane[i] = 0.0f;
    if (threadIdx.x < 3) g_glob[threadIdx.x] = 0.0;
    if (threadIdx.x == 0) g_count = 0u;
}

extern "C" void kernel_launch(void* const* d_in, const int* in_sizes, int n_in,
                              void* d_out, int out_size) {
    const float4* pred = (const float4*)d_in[0];
    const float4* tgt  = (const float4*)d_in[1];
    composite_kernel<<<PLANES * SEGS, THREADS>>>(pred, tgt, (float*)d_out, out_size);
}